// round 14
// baseline (speedup 1.0000x reference)
#include <cuda_runtime.h>
#include <cuda_fp16.h>
#include <math.h>
#include <stdint.h>

// ---------------- problem constants ----------------
#define BATCH   32
#define IMGSZ   224
#define PATCH   16
#define CC      384
#define DD      12
#define TT      8
#define HIDN    1536
#define NCLS    1000
#define GRIDW   14
#define NTOK    (BATCH*GRIDW*GRIDW)   // 6272
#define KI2C    (PATCH*PATCH*3)       // 768

// weight scratch offsets (elements; chunked [M/128][K/32] 8KB blocks)
#define OFF_PATCH   0
#define LEN_PATCH   (384*768)
#define OFF_BLK0    LEN_PATCH
#define LEN_CXC     (CC*CC)            // 147456
#define LEN_W1      (HIDN*CC)          // 589824
#define PER_BLK     (2*LEN_CXC + 2*LEN_W1)   // 1474560
#define WT_TOTAL    (OFF_BLK0 + DD*PER_BLK)  // 17989632

// ---------------- scratch (no allocations allowed) ----------------
__device__ float g_h   [(size_t)NTOK*CC];
__device__ float g_z   [(size_t)NTOK*CC];
__device__ float g_pool[(size_t)BATCH*CC];
__device__ __half g_uh [(size_t)NTOK*CC];      // u (fp16)
__device__ __half g_gh [(size_t)NTOK*CC];      // gate (fp16)
__device__ __half g_za [(size_t)NTOK*KI2C];    // A operand, chunked layout
__device__ __half g_hid[(size_t)NTOK*HIDN];    // MLP hidden, chunked layout
__device__ __half g_wt [(size_t)WT_TOTAL];     // weights, chunked layout

// ---------------- chunked layout ----------------
__device__ __forceinline__ size_t coff(int row, int k, int Kdim) {
    int rk = row & 127;
    int seg = (k >> 3) & 3, col = k & 7;
    return (((size_t)((row >> 7) * (Kdim >> 5) + (k >> 5))) << 13)
         + (uint32_t)(rk * 64 + ((seg ^ ((rk >> 1) & 3)) << 4) + col * 2);
}

// ---------------- small helpers ----------------
// gelu(x) = 0.5x(1+tanh(z)) == x * sigmoid(2z), z = 0.79788456*(x + 0.044715 x^3)
__device__ __forceinline__ float gelu_f(float x) {
    float z2 = 1.5957691216057308f * x * fmaf(0.044715f, x * x, 1.0f);
    return x * (1.0f / (1.0f + __expf(-z2)));
}
__device__ __forceinline__ float sigmoid_f(float x) { return 1.0f / (1.0f + __expf(-x)); }

__device__ __forceinline__ uint32_t smem_u32(const void* p) {
    uint32_t a;
    asm("{ .reg .u64 t; cvta.to.shared.u64 t, %1; cvt.u32.u64 %0, t; }" : "=r"(a) : "l"(p));
    return a;
}
__device__ __forceinline__ uint32_t packh2(float a, float b) {
    __half2 h = __halves2half2(__float2half_rn(a), __float2half_rn(b));
    return *reinterpret_cast<uint32_t*>(&h);
}
__device__ __forceinline__ float4 fma4(float4 a, float4 b, float4 c) {
    float4 r;
    r.x = fmaf(a.x, b.x, c.x); r.y = fmaf(a.y, b.y, c.y);
    r.z = fmaf(a.z, b.z, c.z); r.w = fmaf(a.w, b.w, c.w);
    return r;
}
__device__ __forceinline__ float4 h4_to_f4(uint2 p) {
    __half2 h0 = *reinterpret_cast<__half2*>(&p.x);
    __half2 h1 = *reinterpret_cast<__half2*>(&p.y);
    float2 f0 = __half22float2(h0), f1 = __half22float2(h1);
    float4 r; r.x = f0.x; r.y = f0.y; r.z = f1.x; r.w = f1.y;
    return r;
}

#define MBAR_INIT(a, c)  asm volatile("mbarrier.init.shared.b64 [%0], %1;" :: "r"(a), "r"(c) : "memory")
#define MBAR_EXPECT(a, tx) asm volatile("mbarrier.arrive.expect_tx.shared.b64 _, [%0], %1;" :: "r"(a), "r"(tx) : "memory")

__device__ __forceinline__ void bulk_ld(uint32_t dst, const void* src, uint32_t bytes, uint32_t mbar) {
    asm volatile("cp.async.bulk.shared::cluster.global.mbarrier::complete_tx::bytes [%0], [%1], %2, [%3];"
                 :: "r"(dst), "l"(src), "r"(bytes), "r"(mbar) : "memory");
}

__device__ __forceinline__ void mbar_wait(uint32_t mbar, uint32_t parity) {
    uint32_t done;
    asm volatile("{\n\t.reg .pred p;\n\t"
                 "mbarrier.try_wait.parity.acquire.cta.shared::cta.b64 p, [%1], %2;\n\t"
                 "selp.b32 %0, 1, 0, p;\n\t}"
                 : "=r"(done) : "r"(mbar), "r"(parity) : "memory");
    if (!done) {
        asm volatile("{\n\t.reg .pred P1;\n\t"
                     "WL_%=:\n\t"
                     "mbarrier.try_wait.parity.acquire.cta.shared::cta.b64 P1, [%0], %1, 0x989680;\n\t"
                     "@P1 bra.uni WD_%=;\n\t"
                     "bra.uni WL_%=;\n\t"
                     "WD_%=:\n\t}" :: "r"(mbar), "r"(parity) : "memory");
    }
}

__device__ __forceinline__ void ldm4(uint32_t* r, uint32_t addr) {
    asm volatile("ldmatrix.sync.aligned.m8n8.x4.shared.b16 {%0,%1,%2,%3}, [%4];"
                 : "=r"(r[0]), "=r"(r[1]), "=r"(r[2]), "=r"(r[3]) : "r"(addr));
}
__device__ __forceinline__ void mma16816(float* c, const uint32_t* a, const uint32_t* b) {
    asm volatile("mma.sync.aligned.m16n8k16.row.col.f32.f16.f16.f32 "
                 "{%0,%1,%2,%3}, {%4,%5,%6,%7}, {%8,%9}, {%0,%1,%2,%3};"
                 : "+f"(c[0]), "+f"(c[1]), "+f"(c[2]), "+f"(c[3])
                 : "r"(a[0]), "r"(a[1]), "r"(a[2]), "r"(a[3]), "r"(b[0]), "r"(b[1]));
}

// ---------------- weight convert+transpose into chunked layout ----------------
__global__ __launch_bounds__(256)
void convert_w_kernel(const float* __restrict__ patch_w,
                      const float* __restrict__ w_in, const float* __restrict__ w_g,
                      const float* __restrict__ w1, const float* __restrict__ w2) {
    int id = blockIdx.y;
    const float* src; int K, M; size_t dstel;
    if (id == 0) { src = patch_w; K = KI2C; M = CC; dstel = OFF_PATCH; }
    else {
        int d = (id - 1) >> 2, kind = (id - 1) & 3;
        size_t base = OFF_BLK0 + (size_t)d * PER_BLK;
        if      (kind == 0) { src = w_in + (size_t)d*CC*CC;   K = CC;   M = CC;   dstel = base; }
        else if (kind == 1) { src = w_g  + (size_t)d*CC*CC;   K = CC;   M = CC;   dstel = base + LEN_CXC; }
        else if (kind == 2) { src = w1   + (size_t)d*CC*HIDN; K = CC;   M = HIDN; dstel = base + 2*LEN_CXC; }
        else                { src = w2   + (size_t)d*HIDN*CC; K = HIDN; M = CC;   dstel = base + 2*LEN_CXC + LEN_W1; }
    }
    int nch = (M >> 7) * (K >> 5);
    int ch = blockIdx.x;
    if (ch >= nch) return;
    int mt = ch / (K >> 5), kc = ch % (K >> 5);

    __shared__ __half hs[4096];
    int tid = threadIdx.x;
    #pragma unroll
    for (int it = 0; it < 16; it++) {
        int e = tid + it * 256;
        int kk = e >> 7, rm = e & 127;
        float v = src[(size_t)(kc*32 + kk) * M + mt*128 + rm];
        int seg = kk >> 3, col = kk & 7;
        hs[rm*32 + ((seg ^ ((rm >> 1) & 3)) << 3) + col] = __float2half_rn(v);
    }
    __syncthreads();
    uint4* dst = reinterpret_cast<uint4*>(reinterpret_cast<uint8_t*>(g_wt) + dstel*2 + (size_t)ch*8192);
    const uint4* s4 = reinterpret_cast<const uint4*>(hs);
    dst[tid] = s4[tid];
    dst[tid + 256] = s4[tid + 256];
}

// ---------------- im2col -> fp16 chunked ----------------
__global__ void im2col_kernel(const float* __restrict__ x) {
    int token = blockIdx.x;
    int b  = token / (GRIDW*GRIDW);
    int p  = token % (GRIDW*GRIDW);
    int gy = p / GRIDW, gx = p % GRIDW;
    uint8_t* za = reinterpret_cast<uint8_t*>(g_za);
    for (int k = threadIdx.x; k < KI2C; k += blockDim.x) {
        int py = k / 48;
        int r  = k % 48;
        size_t src = ((size_t)(b*IMGSZ + gy*PATCH + py) * IMGSZ + gx*PATCH) * 3 + r;
        *reinterpret_cast<__half*>(za + coff(token, k, KI2C)) = __float2half_rn(x[src]);
    }
}

// ---------------- bulk-copy GEMM (BK=64 big-chunks) ----------------
// EPI: 2 gelu->g_hid(chunked) ; 5 fused u/gate (fp16 out) ;
//      6 split-K atomicAdd into residual (gridDim.z=2, +bias on z==0) ;
//      7 split-K atomicAdd +bias+pos on z==0 (patch embed; g_h pre-zeroed)
#define CHUNKB  8192
#define BIGB    (2*CHUNKB)
#define STAGEB  (2*BIGB)
#define NSTAGE  3
#define GEMM_SMEM (NSTAGE*STAGEB + 64)

template<int EPI>
__global__ __launch_bounds__(256, 2)
void tgemm_kernel(const uint8_t* __restrict__ Ab, const uint8_t* __restrict__ Bb,
                  const float* __restrict__ bias, float* __restrict__ Cout,
                  int K, int M, const float* __restrict__ extra) {
    extern __shared__ char smem[];
    const uint32_t sb  = smem_u32(smem);
    const uint32_t mb0 = sb + NSTAGE*STAGEB;
    const int tid = threadIdx.x, wid = tid >> 5, lid = tid & 31;
    const int bn = blockIdx.x, bm = blockIdx.y;
    const int NCfull = K >> 5;
    const int NCsl   = (EPI >= 6) ? (NCfull >> 1) : NCfull;
    const int cb     = (EPI >= 6) ? ((int)blockIdx.z * NCsl) : 0;
    const int NB     = NCsl >> 1;
    const int wm = wid & 1, wn = wid >> 1;

    if (tid == 0) {
        #pragma unroll
        for (int s = 0; s < NSTAGE; s++) MBAR_INIT(mb0 + s*8, 1);
    }
    __syncthreads();

    auto issue = [&](int c, int s) {
        uint32_t mb = mb0 + s*8;
        MBAR_EXPECT(mb, 2*BIGB);
        bulk_ld(sb + s*STAGEB,        Ab + ((size_t)bm*NCfull + cb + 2*c)*CHUNKB, BIGB, mb);
        bulk_ld(sb + s*STAGEB + BIGB, Bb + ((size_t)bn*NCfull + cb + 2*c)*CHUNKB, BIGB, mb);
    };
    if (tid == 0) { issue(0,0); issue(1,1); issue(2,2); }

    float acc[4][4][4];
    #pragma unroll
    for (int i = 0; i < 4; i++)
        #pragma unroll
        for (int j = 0; j < 4; j++)
            #pragma unroll
            for (int q = 0; q < 4; q++) acc[i][j][q] = 0.0f;

    const int arow = lid & 15;
    const int asel = lid >> 4;
    const int brow = (lid & 7) + ((lid & 16) ? 8 : 0);
    const int bsel = (lid >> 3) & 1;

    for (int c = 0; c < NB; c++) {
        const int s = c % NSTAGE;
        mbar_wait(mb0 + s*8, (uint32_t)((c / NSTAGE) & 1));
        #pragma unroll
        for (int sub = 0; sub < 2; sub++) {
            const uint32_t stA = sb + s*STAGEB + sub*CHUNKB;
            const uint32_t stB = sb + s*STAGEB + BIGB + sub*CHUNKB;
            #pragma unroll
            for (int ks = 0; ks < 2; ks++) {
                uint32_t b[4][2];
                #pragma unroll
                for (int ng = 0; ng < 2; ng++) {
                    int row = wn*32 + ng*16 + brow;
                    int seg = ks*2 + bsel;
                    uint32_t r[4];
                    ldm4(r, stB + row*64 + ((seg ^ ((row >> 1) & 3)) << 4));
                    b[ng*2+0][0] = r[0]; b[ng*2+0][1] = r[1];
                    b[ng*2+1][0] = r[2]; b[ng*2+1][1] = r[3];
                }
                #pragma unroll
                for (int mf = 0; mf < 4; mf++) {
                    int row = wm*64 + mf*16 + arow;
                    int seg = ks*2 + asel;
                    uint32_t a[4];
                    ldm4(a, stA + row*64 + ((seg ^ ((row >> 1) & 3)) << 4));
                    #pragma unroll
                    for (int nf = 0; nf < 4; nf++)
                        mma16816(acc[mf][nf], a, b[nf]);
                }
            }
        }
        __syncthreads();
        if (tid == 0 && c + NSTAGE < NB) issue(c + NSTAGE, s);
    }

    // epilogue
    const int gr = lid >> 2, gc = lid & 3;
    uint8_t* hidb = reinterpret_cast<uint8_t*>(g_hid);
    #pragma unroll
    for (int mf = 0; mf < 4; mf++) {
        #pragma unroll
        for (int nf = 0; nf < 4; nf++) {
            const int col = bn * 128 + wn * 32 + nf * 8 + gc * 2;
            #pragma unroll
            for (int half = 0; half < 2; half++) {
                const int row = bm * 128 + wm * 64 + mf * 16 + gr + half * 8;
                float v0 = acc[mf][nf][half*2+0];
                float v1 = acc[mf][nf][half*2+1];
                if (EPI == 6 || EPI == 7) {
                    if (blockIdx.z == 0) {
                        float2 bv = *reinterpret_cast<const float2*>(bias + col);
                        v0 += bv.x; v1 += bv.y;
                        if (EPI == 7) {
                            int p = row % (GRIDW*GRIDW);
                            float2 pv = *reinterpret_cast<const float2*>(extra + (size_t)p * CC + col);
                            v0 += pv.x; v1 += pv.y;
                        }
                    }
                    float* cp = Cout + (size_t)row * M + col;
                    atomicAdd(cp,     v0);
                    atomicAdd(cp + 1, v1);
                    continue;
                }
                if (EPI == 5) {
                    if (col < CC) {
                        float2 bv = *reinterpret_cast<const float2*>(bias + col);
                        *reinterpret_cast<uint32_t*>(&g_uh[(size_t)row * CC + col]) =
                            packh2(v0 + bv.x, v1 + bv.y);
                    } else {
                        int cg = col - CC;
                        float2 bv = *reinterpret_cast<const float2*>(extra + cg);
                        *reinterpret_cast<uint32_t*>(&g_gh[(size_t)row * CC + cg]) =
                            packh2(sigmoid_f(v0 + bv.x), sigmoid_f(v1 + bv.y));
                    }
                    continue;
                }
                if (EPI == 2) {
                    float2 bv = *reinterpret_cast<const float2*>(bias + col);
                    v0 = gelu_f(v0 + bv.x); v1 = gelu_f(v1 + bv.y);
                    *reinterpret_cast<uint32_t*>(hidb + coff(row, col, HIDN)) = packh2(v0, v1);
                    continue;
                }
            }
        }
    }
}

// ---------------- LayerNorm (warp per row) ----------------
template<bool PAIR>
__global__ __launch_bounds__(256)
void ln_kernel(const float* __restrict__ gamma, const float* __restrict__ beta) {
    int row = blockIdx.x * 8 + (threadIdx.x >> 5);
    int lane = threadIdx.x & 31;
    const float* xr = g_h + (size_t)row * CC;
    float4 v[3];
    float s = 0.0f, q = 0.0f;
    #pragma unroll
    for (int i = 0; i < 3; i++) {
        v[i] = *reinterpret_cast<const float4*>(xr + lane*4 + i*128);
        s += v[i].x + v[i].y + v[i].z + v[i].w;
        q += v[i].x*v[i].x + v[i].y*v[i].y + v[i].z*v[i].z + v[i].w*v[i].w;
    }
    #pragma unroll
    for (int o = 16; o; o >>= 1) {
        s += __shfl_xor_sync(0xffffffffu, s, o);
        q += __shfl_xor_sync(0xffffffffu, q, o);
    }
    float m = s * (1.0f / CC);
    float r = rsqrtf(q * (1.0f / CC) - m*m + 1e-6f);
    uint8_t* za = reinterpret_cast<uint8_t*>(g_za);
    #pragma unroll
    for (int i = 0; i < 3; i++) {
        int k = lane*4 + i*128;
        float4 g4 = *reinterpret_cast<const float4*>(gamma + k);
        float4 b4 = *reinterpret_cast<const float4*>(beta + k);
        float y0 = (v[i].x - m) * r * g4.x + b4.x;
        float y1 = (v[i].y - m) * r * g4.y + b4.y;
        float y2 = (v[i].z - m) * r * g4.z + b4.z;
        float y3 = (v[i].w - m) * r * g4.w + b4.w;
        if (PAIR) {
            uint2 p; p.x = packh2(y0, y1); p.y = packh2(y2, y3);
            *reinterpret_cast<uint2*>(za + coff(row, k, CC)) = p;
        } else {
            float4 o; o.x = y0; o.y = y1; o.z = y2; o.w = y3;
            *reinterpret_cast<float4*>(g_z + (size_t)row * CC + k) = o;
        }
    }
}

// ---------------- gated depthwise-conv recurrence (double-buffered state) ----------------
__global__ __launch_bounds__(196)
void recur_kernel(const float* __restrict__ KD) {
    __shared__ float4 sbuf[2][4][256];
    __shared__ float4 kd4[9][4];

    int blk = blockIdx.x;
    int b   = blk / (CC / 16);
    int cg  = blk % (CC / 16);
    int tid = threadIdx.x;
    int y = tid / GRIDW, x = tid % GRIDW;
    const int base_ch = cg * 16;

    for (int i = tid; i < 2 * 4 * 256; i += 196) {
        float4 z; z.x = z.y = z.z = z.w = 0.0f;
        ((float4*)sbuf)[i] = z;
    }
    if (tid < 36) {
        int tap = tid >> 2, grp = tid & 3;
        kd4[tap][grp] = *reinterpret_cast<const float4*>(KD + tap*CC + base_ch + grp*4);
    }

    size_t gbase = ((size_t)(b * (GRIDW*GRIDW) + tid)) * CC + base_ch;
    float4 gg[4], u1[4], cur[4];
    #pragma unroll
    for (int g = 0; g < 4; g++) {
        float4 gv = h4_to_f4(*reinterpret_cast<const uint2*>(g_gh + gbase + g*4));
        float4 uv = h4_to_f4(*reinterpret_cast<const uint2*>(g_uh + gbase + g*4));
        gg[g] = gv;
        u1[g].x = (1.0f-gv.x)*uv.x; u1[g].y = (1.0f-gv.y)*uv.y;
        u1[g].z = (1.0f-gv.z)*uv.z; u1[g].w = (1.0f-gv.w)*uv.w;
        cur[g] = u1[g];
    }
    __syncthreads();

    const int ip = (y + 1) * 16 + (x + 1);
    #pragma unroll
    for (int g = 0; g < 4; g++) sbuf[0][g][ip] = cur[g];
    __syncthreads();

    int pb = 0;
    for (int step = 0; step < TT - 1; step++) {
        float4 ns[4];
        #pragma unroll
        for (int g = 0; g < 4; g++) {
            const float4* sg = sbuf[pb][g];
            float4 a;
            a.x = kd4[4][g].x * cur[g].x; a.y = kd4[4][g].y * cur[g].y;
            a.z = kd4[4][g].z * cur[g].z; a.w = kd4[4][g].w * cur[g].w;
            a = fma4(kd4[0][g], sg[ip-17], a);
            a = fma4(kd4[1][g], sg[ip-16], a);
            a = fma4(kd4[2][g], sg[ip-15], a);
            a = fma4(kd4[3][g], sg[ip-1],  a);
            a = fma4(kd4[5][g], sg[ip+1],  a);
            a = fma4(kd4[6][g], sg[ip+15], a);
            a = fma4(kd4[7][g], sg[ip+16], a);
            a = fma4(kd4[8][g], sg[ip+17], a);
            ns[g] = fma4(gg[g], a, u1[g]);
        }
        #pragma unroll
        for (int g = 0; g < 4; g++) { cur[g] = ns[g]; sbuf[1-pb][g][ip] = ns[g]; }
        __syncthreads();
        pb ^= 1;
    }

    #pragma unroll
    for (int g = 0; g < 4; g++) {
        float4 h = *reinterpret_cast<const float4*>(g_h + gbase + g*4);
        h.x += cur[g].x; h.y += cur[g].y; h.z += cur[g].z; h.w += cur[g].w;
        *reinterpret_cast<float4*>(g_h + gbase + g*4) = h;
    }
}

// ---------------- final max pool over spatial ----------------
__global__ void maxpool_kernel() {
    int b = blockIdx.x, c = threadIdx.x;
    const float* zb = g_z + (size_t)b * (GRIDW*GRIDW) * CC + c;
    float m = -INFINITY;
    #pragma unroll 4
    for (int p = 0; p < GRIDW*GRIDW; p++) m = fmaxf(m, zb[(size_t)p * CC]);
    g_pool[b * CC + c] = m;
}

// ---------------- classification head ----------------
__global__ void head_kernel(const float* __restrict__ HW, const float* __restrict__ HB,
                            float* __restrict__ out) {
    int idx = blockIdx.x * blockDim.x + threadIdx.x;
    if (idx >= BATCH * NCLS) return;
    int b = idx / NCLS, cls = idx % NCLS;
    const float* pb = g_pool + b * CC;
    float acc = HB[cls];
    #pragma unroll 4
    for (int k = 0; k < CC; k++) acc += pb[k] * HW[(size_t)k * NCLS + cls];
    out[idx] = acc;
}

// ---------------- host orchestration ----------------
extern "C" void kernel_launch(void* const* d_in, const int* in_sizes, int n_in,
                              void* d_out, int out_size) {
    const float* x       = (const float*)d_in[0];
    const float* patch_w = (const float*)d_in[1];
    const float* patch_b = (const float*)d_in[2];
    const float* pos     = (const float*)d_in[3];
    const float* ln1_s   = (const float*)d_in[4];
    const float* ln1_b   = (const float*)d_in[5];
    const float* w_in    = (const float*)d_in[6];
    const float* b_in    = (const float*)d_in[7];
    const float* w_g     = (const float*)d_in[8];
    const float* b_g     = (const float*)d_in[9];
    const float* k_dw    = (const float*)d_in[10];
    const float* ln2_s   = (const float*)d_in[11];
    const float* ln2_b   = (const float*)d_in[12];
    const float* w1      = (const float*)d_in[13];
    const float* b1      = (const float*)d_in[14];
    const float* w2      = (const float*)d_in[15];
    const float* b2      = (const float*)d_in[16];
    const float* lnf_s   = (const float*)d_in[17];
    const float* lnf_b   = (const float*)d_in[18];
    const float* head_w  = (const float*)d_in[19];
    const float* head_b  = (const float*)d_in[20];
    float* out = (float*)d_out;

    float *ph;
    uint8_t *za, *hid, *wt;
    cudaGetSymbolAddress((void**)&ph,  g_h);
    cudaGetSymbolAddress((void**)&za,  g_za);
    cudaGetSymbolAddress((void**)&hid, g_hid);
    cudaGetSymbolAddress((void**)&wt,  g_wt);

    cudaFuncSetAttribute(tgemm_kernel<2>, cudaFuncAttributeMaxDynamicSharedMemorySize, GEMM_SMEM);
    cudaFuncSetAttribute(tgemm_kernel<5>, cudaFuncAttributeMaxDynamicSharedMemorySize, GEMM_SMEM);
    cudaFuncSetAttribute(tgemm_kernel<6>, cudaFuncAttributeMaxDynamicSharedMemorySize, GEMM_SMEM);
    cudaFuncSetAttribute(tgemm_kernel<7>, cudaFuncAttributeMaxDynamicSharedMemorySize, GEMM_SMEM);

    const int NT = NTOK / 128;   // 49

    // weights -> chunked fp16
    convert_w_kernel<<<dim3(144, 1 + 4*DD), 256>>>(patch_w, w_in, w_g, w1, w2);

    // patch embed: zero residual, im2col, split-K x2 GEMM accumulating into g_h
    cudaMemsetAsync(ph, 0, (size_t)NTOK * CC * sizeof(float));
    im2col_kernel<<<NTOK, 256>>>(x);
    tgemm_kernel<7><<<dim3(CC/128, NT, 2), 256, GEMM_SMEM>>>(
        za, wt + (size_t)OFF_PATCH*2, patch_b, ph, KI2C, CC, pos);

    for (int d = 0; d < DD; d++) {
        size_t wb = ((size_t)OFF_BLK0 + (size_t)d * PER_BLK) * 2;
        ln_kernel<true><<<NTOK/8, 256>>>(ln1_s + d*CC, ln1_b + d*CC);
        tgemm_kernel<5><<<dim3((2*CC)/128, NT), 256, GEMM_SMEM>>>(
            za, wt + wb, b_in + d*CC, nullptr, CC, 2*CC, b_g + d*CC);
        recur_kernel<<<BATCH * (CC/16), 196>>>(k_dw + (size_t)d*9*CC);
        ln_kernel<true><<<NTOK/8, 256>>>(ln2_s + d*CC, ln2_b + d*CC);
        tgemm_kernel<2><<<dim3(HIDN/128, NT), 256, GEMM_SMEM>>>(
            za, wt + wb + (size_t)2*LEN_CXC*2, b1 + d*HIDN, nullptr, CC, HIDN, nullptr);
        tgemm_kernel<6><<<dim3(CC/128, NT, 2), 256, GEMM_SMEM>>>(
            hid, wt + wb + (size_t)(2*LEN_CXC + LEN_W1)*2, b2 + d*CC, ph, HIDN, CC, nullptr);
    }

    ln_kernel<false><<<NTOK/8, 256>>>(lnf_s, lnf_b);
    maxpool_kernel<<<BATCH, CC>>>();
    head_kernel<<<(BATCH*NCLS + 255) / 256, 256>>>(head_w, head_b, out);
}

// round 15
// speedup vs baseline: 1.0162x; 1.0162x over previous
#include <cuda_runtime.h>
#include <cuda_fp16.h>
#include <math.h>
#include <stdint.h>

// ---------------- problem constants ----------------
#define BATCH   32
#define IMGSZ   224
#define PATCH   16
#define CC      384
#define DD      12
#define TT      8
#define HIDN    1536
#define NCLS    1000
#define GRIDW   14
#define NTOK    (BATCH*GRIDW*GRIDW)   // 6272
#define KI2C    (PATCH*PATCH*3)       // 768

// weight scratch offsets (elements; chunked [M/128][K/32] 8KB blocks)
#define OFF_PATCH   0
#define LEN_PATCH   (384*768)
#define OFF_BLK0    LEN_PATCH
#define LEN_CXC     (CC*CC)            // 147456
#define LEN_W1      (HIDN*CC)          // 589824
#define PER_BLK     (2*LEN_CXC + 2*LEN_W1)   // 1474560
#define WT_TOTAL    (OFF_BLK0 + DD*PER_BLK)  // 17989632

// ---------------- scratch (no allocations allowed) ----------------
__device__ float g_h   [(size_t)NTOK*CC];
__device__ float g_z   [(size_t)NTOK*CC];
__device__ float g_pool[(size_t)BATCH*CC];
__device__ __half g_uh [(size_t)NTOK*CC];      // u (fp16)
__device__ __half g_gh [(size_t)NTOK*CC];      // gate (fp16)
__device__ __half g_za [(size_t)NTOK*KI2C];    // A operand, chunked layout
__device__ __half g_hid[(size_t)NTOK*HIDN];    // MLP hidden, chunked layout
__device__ __half g_wt [(size_t)WT_TOTAL];     // weights, chunked layout

// ---------------- chunked layout ----------------
__device__ __forceinline__ size_t coff(int row, int k, int Kdim) {
    int rk = row & 127;
    int seg = (k >> 3) & 3, col = k & 7;
    return (((size_t)((row >> 7) * (Kdim >> 5) + (k >> 5))) << 13)
         + (uint32_t)(rk * 64 + ((seg ^ ((rk >> 1) & 3)) << 4) + col * 2);
}

// ---------------- small helpers ----------------
// gelu(x) = 0.5x(1+tanh(z)) == x * sigmoid(2z), z = 0.79788456*(x + 0.044715 x^3)
__device__ __forceinline__ float gelu_f(float x) {
    float z2 = 1.5957691216057308f * x * fmaf(0.044715f, x * x, 1.0f);
    return x * (1.0f / (1.0f + __expf(-z2)));
}
__device__ __forceinline__ float sigmoid_f(float x) { return 1.0f / (1.0f + __expf(-x)); }

__device__ __forceinline__ uint32_t smem_u32(const void* p) {
    uint32_t a;
    asm("{ .reg .u64 t; cvta.to.shared.u64 t, %1; cvt.u32.u64 %0, t; }" : "=r"(a) : "l"(p));
    return a;
}
__device__ __forceinline__ uint32_t packh2(float a, float b) {
    __half2 h = __halves2half2(__float2half_rn(a), __float2half_rn(b));
    return *reinterpret_cast<uint32_t*>(&h);
}
__device__ __forceinline__ float4 fma4(float4 a, float4 b, float4 c) {
    float4 r;
    r.x = fmaf(a.x, b.x, c.x); r.y = fmaf(a.y, b.y, c.y);
    r.z = fmaf(a.z, b.z, c.z); r.w = fmaf(a.w, b.w, c.w);
    return r;
}
__device__ __forceinline__ float4 h4_to_f4(uint2 p) {
    __half2 h0 = *reinterpret_cast<__half2*>(&p.x);
    __half2 h1 = *reinterpret_cast<__half2*>(&p.y);
    float2 f0 = __half22float2(h0), f1 = __half22float2(h1);
    float4 r; r.x = f0.x; r.y = f0.y; r.z = f1.x; r.w = f1.y;
    return r;
}

#define MBAR_INIT(a, c)  asm volatile("mbarrier.init.shared.b64 [%0], %1;" :: "r"(a), "r"(c) : "memory")
#define MBAR_EXPECT(a, tx) asm volatile("mbarrier.arrive.expect_tx.shared.b64 _, [%0], %1;" :: "r"(a), "r"(tx) : "memory")

__device__ __forceinline__ void bulk_ld(uint32_t dst, const void* src, uint32_t bytes, uint32_t mbar) {
    asm volatile("cp.async.bulk.shared::cluster.global.mbarrier::complete_tx::bytes [%0], [%1], %2, [%3];"
                 :: "r"(dst), "l"(src), "r"(bytes), "r"(mbar) : "memory");
}

__device__ __forceinline__ void mbar_wait(uint32_t mbar, uint32_t parity) {
    uint32_t done;
    asm volatile("{\n\t.reg .pred p;\n\t"
                 "mbarrier.try_wait.parity.acquire.cta.shared::cta.b64 p, [%1], %2;\n\t"
                 "selp.b32 %0, 1, 0, p;\n\t}"
                 : "=r"(done) : "r"(mbar), "r"(parity) : "memory");
    if (!done) {
        asm volatile("{\n\t.reg .pred P1;\n\t"
                     "WL_%=:\n\t"
                     "mbarrier.try_wait.parity.acquire.cta.shared::cta.b64 P1, [%0], %1, 0x989680;\n\t"
                     "@P1 bra.uni WD_%=;\n\t"
                     "bra.uni WL_%=;\n\t"
                     "WD_%=:\n\t}" :: "r"(mbar), "r"(parity) : "memory");
    }
}

__device__ __forceinline__ void ldm4(uint32_t* r, uint32_t addr) {
    asm volatile("ldmatrix.sync.aligned.m8n8.x4.shared.b16 {%0,%1,%2,%3}, [%4];"
                 : "=r"(r[0]), "=r"(r[1]), "=r"(r[2]), "=r"(r[3]) : "r"(addr));
}
__device__ __forceinline__ void mma16816(float* c, const uint32_t* a, const uint32_t* b) {
    asm volatile("mma.sync.aligned.m16n8k16.row.col.f32.f16.f16.f32 "
                 "{%0,%1,%2,%3}, {%4,%5,%6,%7}, {%8,%9}, {%0,%1,%2,%3};"
                 : "+f"(c[0]), "+f"(c[1]), "+f"(c[2]), "+f"(c[3])
                 : "r"(a[0]), "r"(a[1]), "r"(a[2]), "r"(a[3]), "r"(b[0]), "r"(b[1]));
}

// ---------------- weight convert+transpose into chunked layout ----------------
__global__ __launch_bounds__(256)
void convert_w_kernel(const float* __restrict__ patch_w,
                      const float* __restrict__ w_in, const float* __restrict__ w_g,
                      const float* __restrict__ w1, const float* __restrict__ w2) {
    int id = blockIdx.y;
    const float* src; int K, M; size_t dstel;
    if (id == 0) { src = patch_w; K = KI2C; M = CC; dstel = OFF_PATCH; }
    else {
        int d = (id - 1) >> 2, kind = (id - 1) & 3;
        size_t base = OFF_BLK0 + (size_t)d * PER_BLK;
        if      (kind == 0) { src = w_in + (size_t)d*CC*CC;   K = CC;   M = CC;   dstel = base; }
        else if (kind == 1) { src = w_g  + (size_t)d*CC*CC;   K = CC;   M = CC;   dstel = base + LEN_CXC; }
        else if (kind == 2) { src = w1   + (size_t)d*CC*HIDN; K = CC;   M = HIDN; dstel = base + 2*LEN_CXC; }
        else                { src = w2   + (size_t)d*HIDN*CC; K = HIDN; M = CC;   dstel = base + 2*LEN_CXC + LEN_W1; }
    }
    int nch = (M >> 7) * (K >> 5);
    int ch = blockIdx.x;
    if (ch >= nch) return;
    int mt = ch / (K >> 5), kc = ch % (K >> 5);

    __shared__ __half hs[4096];
    int tid = threadIdx.x;
    #pragma unroll
    for (int it = 0; it < 16; it++) {
        int e = tid + it * 256;
        int kk = e >> 7, rm = e & 127;
        float v = src[(size_t)(kc*32 + kk) * M + mt*128 + rm];
        int seg = kk >> 3, col = kk & 7;
        hs[rm*32 + ((seg ^ ((rm >> 1) & 3)) << 3) + col] = __float2half_rn(v);
    }
    __syncthreads();
    uint4* dst = reinterpret_cast<uint4*>(reinterpret_cast<uint8_t*>(g_wt) + dstel*2 + (size_t)ch*8192);
    const uint4* s4 = reinterpret_cast<const uint4*>(hs);
    dst[tid] = s4[tid];
    dst[tid + 256] = s4[tid + 256];
}

// ---------------- im2col -> fp16 chunked ----------------
__global__ void im2col_kernel(const float* __restrict__ x) {
    int token = blockIdx.x;
    int b  = token / (GRIDW*GRIDW);
    int p  = token % (GRIDW*GRIDW);
    int gy = p / GRIDW, gx = p % GRIDW;
    uint8_t* za = reinterpret_cast<uint8_t*>(g_za);
    for (int k = threadIdx.x; k < KI2C; k += blockDim.x) {
        int py = k / 48;
        int r  = k % 48;
        size_t src = ((size_t)(b*IMGSZ + gy*PATCH + py) * IMGSZ + gx*PATCH) * 3 + r;
        *reinterpret_cast<__half*>(za + coff(token, k, KI2C)) = __float2half_rn(x[src]);
    }
}

// ---------------- bulk-copy GEMM (BK=64 big-chunks) ----------------
// EPI: 2 gelu->g_hid(chunked) ; 4 +bias+pos ; 5 fused u/gate (fp16 out) ;
//      6 split-K atomicAdd into residual (gridDim.z = 2, +bias on z==0)
#define CHUNKB  8192
#define BIGB    (2*CHUNKB)
#define STAGEB  (2*BIGB)
#define NSTAGE  3
#define GEMM_SMEM (NSTAGE*STAGEB + 64)

template<int EPI>
__global__ __launch_bounds__(256, 2)
void tgemm_kernel(const uint8_t* __restrict__ Ab, const uint8_t* __restrict__ Bb,
                  const float* __restrict__ bias, float* __restrict__ Cout,
                  int K, int M, const float* __restrict__ extra) {
    extern __shared__ char smem[];
    const uint32_t sb  = smem_u32(smem);
    const uint32_t mb0 = sb + NSTAGE*STAGEB;
    const int tid = threadIdx.x, wid = tid >> 5, lid = tid & 31;
    const int bn = blockIdx.x, bm = blockIdx.y;
    const int NCfull = K >> 5;
    const int NCsl   = (EPI == 6) ? (NCfull >> 1) : NCfull;
    const int cb     = (EPI == 6) ? ((int)blockIdx.z * NCsl) : 0;
    const int NB     = NCsl >> 1;
    const int wm = wid & 1, wn = wid >> 1;

    if (tid == 0) {
        #pragma unroll
        for (int s = 0; s < NSTAGE; s++) MBAR_INIT(mb0 + s*8, 1);
    }
    __syncthreads();

    auto issue = [&](int c, int s) {
        uint32_t mb = mb0 + s*8;
        MBAR_EXPECT(mb, 2*BIGB);
        bulk_ld(sb + s*STAGEB,        Ab + ((size_t)bm*NCfull + cb + 2*c)*CHUNKB, BIGB, mb);
        bulk_ld(sb + s*STAGEB + BIGB, Bb + ((size_t)bn*NCfull + cb + 2*c)*CHUNKB, BIGB, mb);
    };
    if (tid == 0) { issue(0,0); issue(1,1); issue(2,2); }

    float acc[4][4][4];
    #pragma unroll
    for (int i = 0; i < 4; i++)
        #pragma unroll
        for (int j = 0; j < 4; j++)
            #pragma unroll
            for (int q = 0; q < 4; q++) acc[i][j][q] = 0.0f;

    const int arow = lid & 15;
    const int asel = lid >> 4;
    const int brow = (lid & 7) + ((lid & 16) ? 8 : 0);
    const int bsel = (lid >> 3) & 1;

    for (int c = 0; c < NB; c++) {
        const int s = c % NSTAGE;
        mbar_wait(mb0 + s*8, (uint32_t)((c / NSTAGE) & 1));
        #pragma unroll
        for (int sub = 0; sub < 2; sub++) {
            const uint32_t stA = sb + s*STAGEB + sub*CHUNKB;
            const uint32_t stB = sb + s*STAGEB + BIGB + sub*CHUNKB;
            #pragma unroll
            for (int ks = 0; ks < 2; ks++) {
                uint32_t b[4][2];
                #pragma unroll
                for (int ng = 0; ng < 2; ng++) {
                    int row = wn*32 + ng*16 + brow;
                    int seg = ks*2 + bsel;
                    uint32_t r[4];
                    ldm4(r, stB + row*64 + ((seg ^ ((row >> 1) & 3)) << 4));
                    b[ng*2+0][0] = r[0]; b[ng*2+0][1] = r[1];
                    b[ng*2+1][0] = r[2]; b[ng*2+1][1] = r[3];
                }
                #pragma unroll
                for (int mf = 0; mf < 4; mf++) {
                    int row = wm*64 + mf*16 + arow;
                    int seg = ks*2 + asel;
                    uint32_t a[4];
                    ldm4(a, stA + row*64 + ((seg ^ ((row >> 1) & 3)) << 4));
                    #pragma unroll
                    for (int nf = 0; nf < 4; nf++)
                        mma16816(acc[mf][nf], a, b[nf]);
                }
            }
        }
        __syncthreads();
        if (tid == 0 && c + NSTAGE < NB) issue(c + NSTAGE, s);
    }

    // epilogue
    const int gr = lid >> 2, gc = lid & 3;
    uint8_t* hidb = reinterpret_cast<uint8_t*>(g_hid);
    #pragma unroll
    for (int mf = 0; mf < 4; mf++) {
        #pragma unroll
        for (int nf = 0; nf < 4; nf++) {
            const int col = bn * 128 + wn * 32 + nf * 8 + gc * 2;
            #pragma unroll
            for (int half = 0; half < 2; half++) {
                const int row = bm * 128 + wm * 64 + mf * 16 + gr + half * 8;
                float v0 = acc[mf][nf][half*2+0];
                float v1 = acc[mf][nf][half*2+1];
                if (EPI == 6) {
                    if (blockIdx.z == 0) {
                        float2 bv = *reinterpret_cast<const float2*>(bias + col);
                        v0 += bv.x; v1 += bv.y;
                    }
                    float* cp = Cout + (size_t)row * M + col;
                    atomicAdd(cp,     v0);
                    atomicAdd(cp + 1, v1);
                    continue;
                }
                if (EPI == 5) {
                    if (col < CC) {
                        float2 bv = *reinterpret_cast<const float2*>(bias + col);
                        *reinterpret_cast<uint32_t*>(&g_uh[(size_t)row * CC + col]) =
                            packh2(v0 + bv.x, v1 + bv.y);
                    } else {
                        int cg = col - CC;
                        float2 bv = *reinterpret_cast<const float2*>(extra + cg);
                        *reinterpret_cast<uint32_t*>(&g_gh[(size_t)row * CC + cg]) =
                            packh2(sigmoid_f(v0 + bv.x), sigmoid_f(v1 + bv.y));
                    }
                    continue;
                }
                {
                    float2 bv = *reinterpret_cast<const float2*>(bias + col);
                    v0 += bv.x; v1 += bv.y;
                }
                if (EPI == 2) {
                    v0 = gelu_f(v0); v1 = gelu_f(v1);
                    *reinterpret_cast<uint32_t*>(hidb + coff(row, col, HIDN)) = packh2(v0, v1);
                    continue;
                }
                if (EPI == 4) {
                    int p = row % (GRIDW*GRIDW);
                    float2 pv = *reinterpret_cast<const float2*>(extra + (size_t)p * CC + col);
                    v0 += pv.x; v1 += pv.y;
                }
                float* cp = Cout + (size_t)row * M + col;
                float2 o; o.x = v0; o.y = v1;
                *reinterpret_cast<float2*>(cp) = o;
            }
        }
    }
}

// ---------------- LayerNorm (2 rows per warp, deep MLP) ----------------
template<bool PAIR>
__global__ __launch_bounds__(256)
void ln_kernel(const float* __restrict__ gamma, const float* __restrict__ beta) {
    int w = threadIdx.x >> 5, lane = threadIdx.x & 31;
    int row0 = blockIdx.x * 16 + w * 2;
    const float* xr0 = g_h + (size_t)row0 * CC;
    const float* xr1 = xr0 + CC;
    float4 v0[3], v1[3];
    #pragma unroll
    for (int i = 0; i < 3; i++) v0[i] = *reinterpret_cast<const float4*>(xr0 + lane*4 + i*128);
    #pragma unroll
    for (int i = 0; i < 3; i++) v1[i] = *reinterpret_cast<const float4*>(xr1 + lane*4 + i*128);

    float s0 = 0.f, q0 = 0.f, s1 = 0.f, q1 = 0.f;
    #pragma unroll
    for (int i = 0; i < 3; i++) {
        s0 += v0[i].x + v0[i].y + v0[i].z + v0[i].w;
        q0 += v0[i].x*v0[i].x + v0[i].y*v0[i].y + v0[i].z*v0[i].z + v0[i].w*v0[i].w;
        s1 += v1[i].x + v1[i].y + v1[i].z + v1[i].w;
        q1 += v1[i].x*v1[i].x + v1[i].y*v1[i].y + v1[i].z*v1[i].z + v1[i].w*v1[i].w;
    }
    #pragma unroll
    for (int o = 16; o; o >>= 1) {
        s0 += __shfl_xor_sync(0xffffffffu, s0, o);
        q0 += __shfl_xor_sync(0xffffffffu, q0, o);
        s1 += __shfl_xor_sync(0xffffffffu, s1, o);
        q1 += __shfl_xor_sync(0xffffffffu, q1, o);
    }
    float m0 = s0 * (1.0f / CC), r0 = rsqrtf(q0 * (1.0f / CC) - m0*m0 + 1e-6f);
    float m1 = s1 * (1.0f / CC), r1 = rsqrtf(q1 * (1.0f / CC) - m1*m1 + 1e-6f);
    uint8_t* za = reinterpret_cast<uint8_t*>(g_za);
    #pragma unroll
    for (int i = 0; i < 3; i++) {
        int k = lane*4 + i*128;
        float4 g4 = *reinterpret_cast<const float4*>(gamma + k);
        float4 b4 = *reinterpret_cast<const float4*>(beta + k);
        float a0 = (v0[i].x - m0) * r0 * g4.x + b4.x;
        float a1 = (v0[i].y - m0) * r0 * g4.y + b4.y;
        float a2 = (v0[i].z - m0) * r0 * g4.z + b4.z;
        float a3 = (v0[i].w - m0) * r0 * g4.w + b4.w;
        float c0 = (v1[i].x - m1) * r1 * g4.x + b4.x;
        float c1 = (v1[i].y - m1) * r1 * g4.y + b4.y;
        float c2 = (v1[i].z - m1) * r1 * g4.z + b4.z;
        float c3 = (v1[i].w - m1) * r1 * g4.w + b4.w;
        if (PAIR) {
            uint2 p0; p0.x = packh2(a0, a1); p0.y = packh2(a2, a3);
            uint2 p1; p1.x = packh2(c0, c1); p1.y = packh2(c2, c3);
            *reinterpret_cast<uint2*>(za + coff(row0,     k, CC)) = p0;
            *reinterpret_cast<uint2*>(za + coff(row0 + 1, k, CC)) = p1;
        } else {
            float4 o0; o0.x=a0; o0.y=a1; o0.z=a2; o0.w=a3;
            float4 o1; o1.x=c0; o1.y=c1; o1.z=c2; o1.w=c3;
            *reinterpret_cast<float4*>(g_z + (size_t)row0 * CC + k) = o0;
            *reinterpret_cast<float4*>(g_z + (size_t)(row0+1) * CC + k) = o1;
        }
    }
}

// ---------------- gated depthwise-conv recurrence (double-buffered state) ----------------
__global__ __launch_bounds__(196)
void recur_kernel(const float* __restrict__ KD) {
    __shared__ float4 sbuf[2][4][256];
    __shared__ float4 kd4[9][4];

    int blk = blockIdx.x;
    int b   = blk / (CC / 16);
    int cg  = blk % (CC / 16);
    int tid = threadIdx.x;
    int y = tid / GRIDW, x = tid % GRIDW;
    const int base_ch = cg * 16;

    for (int i = tid; i < 2 * 4 * 256; i += 196) {
        float4 z; z.x = z.y = z.z = z.w = 0.0f;
        ((float4*)sbuf)[i] = z;
    }
    if (tid < 36) {
        int tap = tid >> 2, grp = tid & 3;
        kd4[tap][grp] = *reinterpret_cast<const float4*>(KD + tap*CC + base_ch + grp*4);
    }

    size_t gbase = ((size_t)(b * (GRIDW*GRIDW) + tid)) * CC + base_ch;
    float4 gg[4], u1[4], cur[4];
    #pragma unroll
    for (int g = 0; g < 4; g++) {
        float4 gv = h4_to_f4(*reinterpret_cast<const uint2*>(g_gh + gbase + g*4));
        float4 uv = h4_to_f4(*reinterpret_cast<const uint2*>(g_uh + gbase + g*4));
        gg[g] = gv;
        u1[g].x = (1.0f-gv.x)*uv.x; u1[g].y = (1.0f-gv.y)*uv.y;
        u1[g].z = (1.0f-gv.z)*uv.z; u1[g].w = (1.0f-gv.w)*uv.w;
        cur[g] = u1[g];
    }
    __syncthreads();

    const int ip = (y + 1) * 16 + (x + 1);
    #pragma unroll
    for (int g = 0; g < 4; g++) sbuf[0][g][ip] = cur[g];
    __syncthreads();

    int pb = 0;
    for (int step = 0; step < TT - 1; step++) {
        float4 ns[4];
        #pragma unroll
        for (int g = 0; g < 4; g++) {
            const float4* sg = sbuf[pb][g];
            float4 a;
            a.x = kd4[4][g].x * cur[g].x; a.y = kd4[4][g].y * cur[g].y;
            a.z = kd4[4][g].z * cur[g].z; a.w = kd4[4][g].w * cur[g].w;
            a = fma4(kd4[0][g], sg[ip-17], a);
            a = fma4(kd4[1][g], sg[ip-16], a);
            a = fma4(kd4[2][g], sg[ip-15], a);
            a = fma4(kd4[3][g], sg[ip-1],  a);
            a = fma4(kd4[5][g], sg[ip+1],  a);
            a = fma4(kd4[6][g], sg[ip+15], a);
            a = fma4(kd4[7][g], sg[ip+16], a);
            a = fma4(kd4[8][g], sg[ip+17], a);
            ns[g] = fma4(gg[g], a, u1[g]);
        }
        #pragma unroll
        for (int g = 0; g < 4; g++) { cur[g] = ns[g]; sbuf[1-pb][g][ip] = ns[g]; }
        __syncthreads();
        pb ^= 1;
    }

    #pragma unroll
    for (int g = 0; g < 4; g++) {
        float4 h = *reinterpret_cast<const float4*>(g_h + gbase + g*4);
        h.x += cur[g].x; h.y += cur[g].y; h.z += cur[g].z; h.w += cur[g].w;
        *reinterpret_cast<float4*>(g_h + gbase + g*4) = h;
    }
}

// ---------------- final max pool over spatial ----------------
__global__ void maxpool_kernel() {
    int b = blockIdx.x, c = threadIdx.x;
    const float* zb = g_z + (size_t)b * (GRIDW*GRIDW) * CC + c;
    float m = -INFINITY;
    #pragma unroll 4
    for (int p = 0; p < GRIDW*GRIDW; p++) m = fmaxf(m, zb[(size_t)p * CC]);
    g_pool[b * CC + c] = m;
}

// ---------------- classification head ----------------
__global__ void head_kernel(const float* __restrict__ HW, const float* __restrict__ HB,
                            float* __restrict__ out) {
    int idx = blockIdx.x * blockDim.x + threadIdx.x;
    if (idx >= BATCH * NCLS) return;
    int b = idx / NCLS, cls = idx % NCLS;
    const float* pb = g_pool + b * CC;
    float acc = HB[cls];
    #pragma unroll 4
    for (int k = 0; k < CC; k++) acc += pb[k] * HW[(size_t)k * NCLS + cls];
    out[idx] = acc;
}

// ---------------- host orchestration ----------------
extern "C" void kernel_launch(void* const* d_in, const int* in_sizes, int n_in,
                              void* d_out, int out_size) {
    const float* x       = (const float*)d_in[0];
    const float* patch_w = (const float*)d_in[1];
    const float* patch_b = (const float*)d_in[2];
    const float* pos     = (const float*)d_in[3];
    const float* ln1_s   = (const float*)d_in[4];
    const float* ln1_b   = (const float*)d_in[5];
    const float* w_in    = (const float*)d_in[6];
    const float* b_in    = (const float*)d_in[7];
    const float* w_g     = (const float*)d_in[8];
    const float* b_g     = (const float*)d_in[9];
    const float* k_dw    = (const float*)d_in[10];
    const float* ln2_s   = (const float*)d_in[11];
    const float* ln2_b   = (const float*)d_in[12];
    const float* w1      = (const float*)d_in[13];
    const float* b1      = (const float*)d_in[14];
    const float* w2      = (const float*)d_in[15];
    const float* b2      = (const float*)d_in[16];
    const float* lnf_s   = (const float*)d_in[17];
    const float* lnf_b   = (const float*)d_in[18];
    const float* head_w  = (const float*)d_in[19];
    const float* head_b  = (const float*)d_in[20];
    float* out = (float*)d_out;

    float *ph;
    uint8_t *za, *hid, *wt;
    cudaGetSymbolAddress((void**)&ph,  g_h);
    cudaGetSymbolAddress((void**)&za,  g_za);
    cudaGetSymbolAddress((void**)&hid, g_hid);
    cudaGetSymbolAddress((void**)&wt,  g_wt);

    cudaFuncSetAttribute(tgemm_kernel<2>, cudaFuncAttributeMaxDynamicSharedMemorySize, GEMM_SMEM);
    cudaFuncSetAttribute(tgemm_kernel<4>, cudaFuncAttributeMaxDynamicSharedMemorySize, GEMM_SMEM);
    cudaFuncSetAttribute(tgemm_kernel<5>, cudaFuncAttributeMaxDynamicSharedMemorySize, GEMM_SMEM);
    cudaFuncSetAttribute(tgemm_kernel<6>, cudaFuncAttributeMaxDynamicSharedMemorySize, GEMM_SMEM);

    const int NT = NTOK / 128;   // 49

    // weights -> chunked fp16
    convert_w_kernel<<<dim3(144, 1 + 4*DD), 256>>>(patch_w, w_in, w_g, w1, w2);

    // patch embed
    im2col_kernel<<<NTOK, 256>>>(x);
    tgemm_kernel<4><<<dim3(CC/128, NT), 256, GEMM_SMEM>>>(
        za, wt + (size_t)OFF_PATCH*2, patch_b, ph, KI2C, CC, pos);

    for (int d = 0; d < DD; d++) {
        size_t wb = ((size_t)OFF_BLK0 + (size_t)d * PER_BLK) * 2;
        ln_kernel<true><<<NTOK/16, 256>>>(ln1_s + d*CC, ln1_b + d*CC);
        tgemm_kernel<5><<<dim3((2*CC)/128, NT), 256, GEMM_SMEM>>>(
            za, wt + wb, b_in + d*CC, nullptr, CC, 2*CC, b_g + d*CC);
        recur_kernel<<<BATCH * (CC/16), 196>>>(k_dw + (size_t)d*9*CC);
        ln_kernel<true><<<NTOK/16, 256>>>(ln2_s + d*CC, ln2_b + d*CC);
        tgemm_kernel<2><<<dim3(HIDN/128, NT), 256, GEMM_SMEM>>>(
            za, wt + wb + (size_t)2*LEN_CXC*2, b1 + d*HIDN, nullptr, CC, HIDN, nullptr);
        tgemm_kernel<6><<<dim3(CC/128, NT, 2), 256, GEMM_SMEM>>>(
            hid, wt + wb + (size_t)(2*LEN_CXC + LEN_W1)*2, b2 + d*CC, ph, HIDN, CC, nullptr);
    }

    ln_kernel<false><<<NTOK/16, 256>>>(lnf_s, lnf_b);
    maxpool_kernel<<<BATCH, CC>>>();
    head_kernel<<<(BATCH*NCLS + 255) / 256, 256>>>(head_w, head_b, out);
}